// round 6
// baseline (speedup 1.0000x reference)
#include <cuda_runtime.h>
#include <math.h>

#define KD   64
#define NE   1024
#define NROW 65536
#define NZ   4194304   // 65536*64

// ---------------- scratch (no allocations allowed) ----------------
__device__ float  g_enorm[NE];
__device__ int    g_counts[NE];
__device__ double g_mse;
__device__ double g_ed;

// ---------------- f32x2 helpers (Blackwell packed fp32) ----------------
__device__ __forceinline__ unsigned long long dup2(float x) {
    unsigned long long r;
    asm("mov.b64 %0, {%1, %1};" : "=l"(r) : "f"(x));
    return r;
}
__device__ __forceinline__ void ffma2(unsigned long long& d, unsigned long long a, unsigned long long b) {
    asm("fma.rn.f32x2 %0, %1, %2, %0;" : "+l"(d) : "l"(a), "l"(b));
}
__device__ __forceinline__ void unpack2(unsigned long long v, float& lo, float& hi) {
    asm("mov.b64 {%0, %1}, %2;" : "=f"(lo), "=f"(hi) : "l"(v));
}

// ---------------- init: e-norms, zero scratch ----------------
// en must be bit-identical to jnp.sum(emb**2, axis=1): square ROUNDED separately,
// then sequential ascending-k adds. No FMA contraction (intrinsics forbid it).
__global__ void vq_init(const float* __restrict__ emb) {
    int t = blockIdx.x * blockDim.x + threadIdx.x;   // 0..1023
    const float* e = emb + (size_t)t * KD;
    float s = 0.f;
    #pragma unroll
    for (int k = 0; k < KD; k++) s = __fadd_rn(s, __fmul_rn(e[k], e[k]));
    g_enorm[t]  = s;
    g_counts[t] = 0;
    if (t == 0) { g_mse = 0.0; g_ed = 0.0; }
}

// ---------------- codebook pairwise-distance sum ----------------
// sum over ALL (i,j) of e_d, halved later (e_d symmetric, diag ~ 0; its tiny
// contribution to the mean is negligible for e_loss).
__global__ __launch_bounds__(256) void vq_ed(const float* __restrict__ emb) {
    __shared__ __align__(16) float Ei[64][65];
    __shared__ __align__(16) float Ej[64][65];
    const int tid = threadIdx.x;
    const int bi = blockIdx.x, bj = blockIdx.y;

    #pragma unroll
    for (int i = 0; i < 4; i++) {
        int idx = tid + i * 256;        // 0..1023
        int r  = idx >> 4;              // 0..63
        int kq = idx & 15;              // 0..15
        float4 v = *reinterpret_cast<const float4*>(emb + (size_t)(bi * 64 + r) * KD + kq * 4);
        Ei[r][kq * 4 + 0] = v.x; Ei[r][kq * 4 + 1] = v.y;
        Ei[r][kq * 4 + 2] = v.z; Ei[r][kq * 4 + 3] = v.w;
        float4 w = *reinterpret_cast<const float4*>(emb + (size_t)(bj * 64 + r) * KD + kq * 4);
        Ej[r][kq * 4 + 0] = w.x; Ej[r][kq * 4 + 1] = w.y;
        Ej[r][kq * 4 + 2] = w.z; Ej[r][kq * 4 + 3] = w.w;
    }
    __syncthreads();

    const int il = tid & 63;
    const int jg = tid >> 6;            // 0..3
    float acc[16];
    #pragma unroll
    for (int jj = 0; jj < 16; jj++) acc[jj] = 0.f;

    for (int k = 0; k < KD; k++) {      // ascending-k FMA chain (matches GEMM microkernel)
        float a = Ei[il][k];
        #pragma unroll
        for (int jj = 0; jj < 16; jj++) acc[jj] = __fmaf_rn(a, Ej[jg * 16 + jj][k], acc[jj]);
    }

    float eni = g_enorm[bi * 64 + il];
    float s = 0.f;
    #pragma unroll
    for (int jj = 0; jj < 16; jj++) {
        int j = jg * 16 + jj;
        float t  = __fadd_rn(eni, g_enorm[bj * 64 + j]);   // fl(en_i + en_j)
        float d2 = __fmaf_rn(-2.f, acc[jj], t);            // fl(t - 2*dot): 2*dot exact
        s += sqrtf(fmaxf(d2, 0.f));
    }
    #pragma unroll
    for (int off = 16; off > 0; off >>= 1) s += __shfl_down_sync(0xffffffffu, s, off);
    if ((tid & 31) == 0) atomicAdd(&g_ed, (double)s);
}

// ---------------- main: distance GEMM + argmin + gather + MSE ----------------
__global__ __launch_bounds__(256, 2) void vq_main(const float* __restrict__ z,
                                                  const float* __restrict__ emb,
                                                  float* __restrict__ out) {
    __shared__ __align__(16) float zsT[KD][128];   // 32 KB, z tile transposed [k][row]
    __shared__ __align__(16) float es[KD][64];     // 16 KB, emb chunk transposed; reused for reduction

    const int tid = threadIdx.x;
    const int tx  = tid & 15;        // code group (4 codes each)
    const int ty  = tid >> 4;        // row group  (8 rows each)
    const int rowBase = blockIdx.x * 128;

    // load z tile transposed (once per block, reused over all 16 code chunks)
    #pragma unroll
    for (int i = 0; i < 8; i++) {
        int idx = tid + i * 256;     // 0..2047
        int r  = idx & 127;
        int kq = idx >> 7;           // 0..15
        float4 v = *reinterpret_cast<const float4*>(z + (size_t)(rowBase + r) * KD + kq * 4);
        zsT[kq * 4 + 0][r] = v.x; zsT[kq * 4 + 1][r] = v.y;
        zsT[kq * 4 + 2][r] = v.z; zsT[kq * 4 + 3][r] = v.w;
    }
    __syncthreads();

    // ||z||^2 per row: MUST bit-match jnp.sum(zf**2, axis=1):
    // rounded square, then sequential ascending-k fp32 adds, NO fma contraction.
    // (A's exact bits set the d ulp-grid; ~215 rows have grid ties whose
    //  first-index resolution must match the reference's.)
    float Ar[8];
    #pragma unroll
    for (int rr = 0; rr < 8; rr++) {
        float s = 0.f;
        int r = ty * 8 + rr;
        for (int k = 0; k < KD; k++) {
            float v = zsT[k][r];
            s = __fadd_rn(s, __fmul_rn(v, v));
        }
        Ar[rr] = s;
    }

    float minv[8]; int mini[8];
    #pragma unroll
    for (int rr = 0; rr < 8; rr++) { minv[rr] = 3.4e38f; mini[rr] = 0; }

    // software-pipelined emb chunk fetch: regs for chunk ch+1 load during chunk ch compute
    float4 pre[4];
    #pragma unroll
    for (int i = 0; i < 4; i++) {
        int idx = tid + i * 256;
        pre[i] = *reinterpret_cast<const float4*>(
            emb + (size_t)(idx & 63) * KD + (idx >> 6) * 4);
    }

    for (int ch = 0; ch < 16; ch++) {
        __syncthreads();             // prior k-loop reads of es must complete
        // stage prefetched chunk into smem (transposed)
        #pragma unroll
        for (int i = 0; i < 4; i++) {
            int idx = tid + i * 256; // 0..1023
            int c  = idx & 63;
            int kq = idx >> 6;       // 0..15
            es[kq * 4 + 0][c] = pre[i].x; es[kq * 4 + 1][c] = pre[i].y;
            es[kq * 4 + 2][c] = pre[i].z; es[kq * 4 + 3][c] = pre[i].w;
        }
        __syncthreads();

        // issue next chunk's gmem loads now; they complete behind the k-loop
        if (ch < 15) {
            const int nb = (ch + 1) * 64;
            #pragma unroll
            for (int i = 0; i < 4; i++) {
                int idx = tid + i * 256;
                pre[i] = *reinterpret_cast<const float4*>(
                    emb + (size_t)(nb + (idx & 63)) * KD + (idx >> 6) * 4);
            }
        }

        const int chBase = ch * 64;
        unsigned long long acc[4][4];
        #pragma unroll
        for (int p = 0; p < 4; p++)
            #pragma unroll
            for (int c = 0; c < 4; c++) acc[p][c] = 0ULL;

        #pragma unroll 16
        for (int k = 0; k < KD; k++) {
            // a-loads are ty-uniform across the 16 tx lanes -> smem broadcast dedup
            const double* ap = reinterpret_cast<const double*>(&zsT[k][ty * 8]);
            unsigned long long a0 = __double_as_longlong(ap[0]);
            unsigned long long a1 = __double_as_longlong(ap[1]);
            unsigned long long a2 = __double_as_longlong(ap[2]);
            unsigned long long a3 = __double_as_longlong(ap[3]);
            float4 bv = *reinterpret_cast<const float4*>(&es[k][tx * 4]);
            unsigned long long b0 = dup2(bv.x), b1 = dup2(bv.y), b2 = dup2(bv.z), b3 = dup2(bv.w);
            ffma2(acc[0][0], a0, b0); ffma2(acc[0][1], a0, b1); ffma2(acc[0][2], a0, b2); ffma2(acc[0][3], a0, b3);
            ffma2(acc[1][0], a1, b0); ffma2(acc[1][1], a1, b1); ffma2(acc[1][2], a1, b2); ffma2(acc[1][3], a1, b3);
            ffma2(acc[2][0], a2, b0); ffma2(acc[2][1], a2, b1); ffma2(acc[2][2], a2, b2); ffma2(acc[2][3], a2, b3);
            ffma2(acc[3][0], a3, b0); ffma2(acc[3][1], a3, b1); ffma2(acc[3][2], a3, b2); ffma2(acc[3][3], a3, b3);
        }

        // d = fl(fl(A + en) - 2*dot) — same rounding structure as the reference
        #pragma unroll
        for (int c = 0; c < 4; c++) {
            int code = chBase + tx * 4 + c;
            float en = g_enorm[code];
            #pragma unroll
            for (int p = 0; p < 4; p++) {
                float lo, hi;
                unpack2(acc[p][c], lo, hi);
                float t0 = __fadd_rn(Ar[2 * p],     en);
                float t1 = __fadd_rn(Ar[2 * p + 1], en);
                float d0 = __fmaf_rn(-2.f, lo, t0);
                float d1 = __fmaf_rn(-2.f, hi, t1);
                if (d0 < minv[2 * p])     { minv[2 * p]     = d0; mini[2 * p]     = code; }
                if (d1 < minv[2 * p + 1]) { minv[2 * p + 1] = d1; mini[2 * p + 1] = code; }
            }
        }
    }

    // cross-thread argmin reduction (reuse es as (val,idx) buffers)
    __syncthreads();
    float* redv = &es[0][0];                          // 2048 floats
    int*   redi = reinterpret_cast<int*>(&es[32][0]); // 2048 ints (disjoint region)
    #pragma unroll
    for (int rr = 0; rr < 8; rr++) {
        redv[(ty * 8 + rr) * 16 + tx] = minv[rr];
        redi[(ty * 8 + rr) * 16 + tx] = mini[rr];
    }
    __syncthreads();

    int bi = 0;
    if (tid < 128) {
        float bv = 3.4e38f; bi = NE;
        #pragma unroll
        for (int t = 0; t < 16; t++) {
            float v = redv[tid * 16 + t];
            int   i = redi[tid * 16 + t];
            if (v < bv || (v == bv && i < bi)) { bv = v; bi = i; }  // first-index tie-break
        }
        int grow = rowBase + tid;
        out[1 + NZ + 1 + grow] = (float)bi;
        atomicAdd(&g_counts[bi], 1);
    }
    __syncthreads();
    if (tid < 128) redi[tid] = bi;   // publish per-row winner
    __syncthreads();

    // coalesced gather + straight-through output + MSE partial
    float msum = 0.f;
    #pragma unroll
    for (int i = 0; i < 32; i++) {
        int flat = i * 256 + tid;          // 0..8191
        int r = flat >> 6, k = flat & 63;
        int b = redi[r];
        float ev = __ldg(emb + (size_t)b * KD + k);
        float zv = __ldg(z + (size_t)(rowBase + r) * KD + k);
        float dd = __fadd_rn(ev, -zv);      // fl(z_q - z)
        msum = __fmaf_rn(dd, dd, msum);
        out[1 + (size_t)(rowBase + r) * KD + k] = __fadd_rn(zv, dd);  // fl(z + fl(z_q - z)) == ref STE
    }
    #pragma unroll
    for (int off = 16; off > 0; off >>= 1) msum += __shfl_down_sync(0xffffffffu, msum, off);
    if ((tid & 31) == 0) atomicAdd(&g_mse, (double)msum);
}

// ---------------- final scalars ----------------
__global__ void vq_final(float* __restrict__ out) {
    __shared__ float warpsum[32];
    int tid = threadIdx.x;   // 1024 threads
    float p = (float)g_counts[tid] * (1.0f / 65536.0f);
    float s = p * logf(p + 1e-10f);
    #pragma unroll
    for (int off = 16; off > 0; off >>= 1) s += __shfl_down_sync(0xffffffffu, s, off);
    if ((tid & 31) == 0) warpsum[tid >> 5] = s;
    __syncthreads();
    if (tid < 32) {
        float v = warpsum[tid];
        #pragma unroll
        for (int off = 16; off > 0; off >>= 1) v += __shfl_down_sync(0xffffffffu, v, off);
        if (tid == 0) {
            float perp  = expf(-v);
            float mse   = (float)(g_mse * (1.0 / (double)NZ));
            float meant = (float)(g_ed * 0.5 / (1024.0 * 1024.0));
            float eloss = expf(-meant * 10.0f);      // exp(-mean/0.1)
            out[0]      = 1.25f * mse + eloss;        // mean + BETA*mean (numerically equal terms)
            out[1 + NZ] = perp;
        }
    }
}

extern "C" void kernel_launch(void* const* d_in, const int* in_sizes, int n_in,
                              void* d_out, int out_size) {
    const float* z   = (const float*)d_in[0];   // (32,32,64,64) fp32
    const float* emb = (const float*)d_in[1];   // (1024,64) fp32
    float* out = (float*)d_out;                 // [loss | z_q_st(4194304) | perplexity | indices(65536)]
    (void)in_sizes; (void)n_in; (void)out_size;

    vq_init<<<8, 128>>>(emb);
    vq_ed<<<dim3(16, 16), 256>>>(emb);
    vq_main<<<512, 256>>>(z, emb, out);
    vq_final<<<1, 1024>>>(out);
}